// round 1
// baseline (speedup 1.0000x reference)
#include <cuda_runtime.h>

// Problem constants
#define T_NB   2
#define T_NP   3
#define T_NC   80
#define T_NH   64
#define T_NW   64
#define T_NM   524288
#define T_HID  64
#define T_NPTS (T_NB * T_NM)   // 1048576

// Transposed planes scratch: [N*P][H][W][C] fp32 (7.86M floats, ~31.5 MB)
__device__ float g_planes_t[T_NB * T_NP * T_NH * T_NW * T_NC];

typedef unsigned long long u64t;

// ---- packed f32x2 helpers (sm_103a FFMA2 path; PTX-only, ptxas won't auto-fuse) ----
static __device__ __forceinline__ u64t pk2(float lo, float hi) {
    u64t r; asm("mov.b64 %0, {%1,%2};" : "=l"(r) : "f"(lo), "f"(hi)); return r;
}
static __device__ __forceinline__ void upk2(u64t v, float& a, float& b) {
    asm("mov.b64 {%0,%1}, %2;" : "=f"(a), "=f"(b) : "l"(v));
}
static __device__ __forceinline__ u64t fma2(u64t a, u64t b, u64t c) {
    u64t d; asm("fma.rn.f32x2 %0, %1, %2, %3;" : "=l"(d) : "l"(a), "l"(b), "l"(c)); return d;
}
static __device__ __forceinline__ u64t mul2(u64t a, u64t b) {
    u64t d; asm("mul.rn.f32x2 %0, %1, %2;" : "=l"(d) : "l"(a), "l"(b)); return d;
}

// Accumulate f * wrow[0..63] into 32 packed f32x2 accumulators (all in registers).
static __device__ __forceinline__ void accum64(float f, const float* __restrict__ wrow, u64t* h) {
    u64t fp = pk2(f, f);
    const ulonglong2* w = (const ulonglong2*)wrow;  // 256B-aligned rows
#pragma unroll
    for (int q = 0; q < 16; q++) {
        ulonglong2 ww = w[q];
        h[2 * q]     = fma2(fp, ww.x, h[2 * q]);
        h[2 * q + 1] = fma2(fp, ww.y, h[2 * q + 1]);
    }
}

// ---------------------------------------------------------------------------
// Kernel A: transpose planes [NP][C][H*W] -> [NP][H*W][C] (tiled, coalesced)
// ---------------------------------------------------------------------------
__global__ void transpose_planes_kernel(const float* __restrict__ in) {
    __shared__ float tile[32][33];
    int np  = blockIdx.z;
    int hw0 = blockIdx.x * 32;
    int c0  = blockIdx.y * 32;
    const float* src = in + np * (T_NC * T_NH * T_NW);
    float* dst = g_planes_t + np * (T_NH * T_NW * T_NC);

    int hw = hw0 + threadIdx.x;
#pragma unroll
    for (int j = 0; j < 32; j += 8) {
        int c = c0 + threadIdx.y + j;
        if (c < T_NC) tile[threadIdx.y + j][threadIdx.x] = src[c * (T_NH * T_NW) + hw];
    }
    __syncthreads();
    int c = c0 + threadIdx.x;
    if (c < T_NC) {
#pragma unroll
        for (int j = 0; j < 32; j += 8) {
            int hww = hw0 + threadIdx.y + j;
            dst[hww * T_NC + c] = tile[threadIdx.x][threadIdx.y + j];
        }
    }
}

// ---------------------------------------------------------------------------
// Kernel B: fused sample + MLP. 1 point/thread, weights in shared (broadcast),
// activations as packed f32x2 register pairs.
// ---------------------------------------------------------------------------
// Shared layout (float offsets); all offsets 8B-aligned.
#define SO_W1 0
#define SO_W2 15360
#define SO_W3 19456
#define SO_W4 23552
#define SO_B1 23616
#define SO_B2 23680
#define SO_B3 23744
#define SO_B4 23808
#define S_FLOATS 23812

__global__ __launch_bounds__(128, 2)
void triplane_mlp_kernel(const float* __restrict__ coords,
                         const float* __restrict__ W1, const float* __restrict__ b1,
                         const float* __restrict__ W2, const float* __restrict__ b2,
                         const float* __restrict__ W3, const float* __restrict__ b3,
                         const float* __restrict__ W4, const float* __restrict__ b4,
                         float* __restrict__ out) {
    extern __shared__ float sm[];
    // cooperative weight load (L2-hit; once per block, persistent blocks)
    for (int i = threadIdx.x; i < 15360; i += 128) sm[SO_W1 + i] = W1[i];
    for (int i = threadIdx.x; i < 4096;  i += 128) sm[SO_W2 + i] = W2[i];
    for (int i = threadIdx.x; i < 4096;  i += 128) sm[SO_W3 + i] = W3[i];
    if (threadIdx.x < 64) {
        sm[SO_W4 + threadIdx.x] = W4[threadIdx.x];
        sm[SO_B1 + threadIdx.x] = b1[threadIdx.x];
        sm[SO_B2 + threadIdx.x] = b2[threadIdx.x];
        sm[SO_B3 + threadIdx.x] = b3[threadIdx.x];
    }
    if (threadIdx.x == 0) sm[SO_B4] = b4[0];
    __syncthreads();

    for (int g = blockIdx.x * 128 + threadIdx.x; g < T_NPTS; g += gridDim.x * 128) {
        int n = g >> 19;  // M = 2^19
        float cx = coords[3 * g + 0];
        float cy = coords[3 * g + 1];
        float cz = coords[3 * g + 2];
        // 2/BOX_WARP == 1.0, so coords are used directly.

        u64t h1[32];
#pragma unroll
        for (int q = 0; q < 32; q++) h1[q] = ((const u64t*)(sm + SO_B1))[q];

#pragma unroll
        for (int p = 0; p < 3; p++) {
            // plane grids: p0:(x,y)  p1:(x,z)  p2:(z,y)
            float u = (p == 2) ? cz : cx;
            float v = (p == 1) ? cz : cy;
            float gx = fmaf(u, 32.f, 31.5f);     // (u+1)*32 - 0.5
            float gy = fmaf(v, 32.f, 31.5f);
            float x0f = floorf(gx), y0f = floorf(gy);
            float fx = gx - x0f, fy = gy - y0f;
            int x0 = (int)x0f, y0 = (int)y0f;
            int x1 = x0 + 1,  y1 = y0 + 1;
            float vx0 = (x0 >= 0 && x0 < 64) ? 1.f : 0.f;
            float vx1 = (x1 >= 0 && x1 < 64) ? 1.f : 0.f;
            float vy0 = (y0 >= 0 && y0 < 64) ? 1.f : 0.f;
            float vy1 = (y1 >= 0 && y1 < 64) ? 1.f : 0.f;
            int xc0 = min(max(x0, 0), 63), xc1 = min(max(x1, 0), 63);
            int yc0 = min(max(y0, 0), 63), yc1 = min(max(y1, 0), 63);
            float wA = (1.f - fx) * (1.f - fy) * vx0 * vy0;  // (x0,y0)
            float wB = fx * (1.f - fy) * vx1 * vy0;          // (x1,y0)
            float wC = (1.f - fx) * fy * vx0 * vy1;          // (x0,y1)
            float wD = fx * fy * vx1 * vy1;                  // (x1,y1)
            u64t wAp = pk2(wA, wA), wBp = pk2(wB, wB);
            u64t wCp = pk2(wC, wC), wDp = pk2(wD, wD);

            int base = (n * 3 + p) * 4096;
            const ulonglong2* pA = (const ulonglong2*)(g_planes_t + (base + yc0 * 64 + xc0) * 80);
            const ulonglong2* pB = (const ulonglong2*)(g_planes_t + (base + yc0 * 64 + xc1) * 80);
            const ulonglong2* pC = (const ulonglong2*)(g_planes_t + (base + yc1 * 64 + xc0) * 80);
            const ulonglong2* pD = (const ulonglong2*)(g_planes_t + (base + yc1 * 64 + xc1) * 80);
            const float* w1p = sm + SO_W1 + p * 80 * T_HID;

            // software-pipelined tap loads: next iteration's LDGs issue before
            // the current accumulate so L2 latency hides under ~300cyc of FMA.
            ulonglong2 a = pA[0], b = pB[0], c = pC[0], d = pD[0];
            for (int c4 = 0; c4 < 20; c4++) {
                ulonglong2 na, nb, nc, nd;
                if (c4 < 19) { na = pA[c4 + 1]; nb = pB[c4 + 1]; nc = pC[c4 + 1]; nd = pD[c4 + 1]; }
                u64t f01 = fma2(wAp, a.x, fma2(wBp, b.x, fma2(wCp, c.x, mul2(wDp, d.x))));
                u64t f23 = fma2(wAp, a.y, fma2(wBp, b.y, fma2(wCp, c.y, mul2(wDp, d.y))));
                float f0, f1, f2, f3;
                upk2(f01, f0, f1); upk2(f23, f2, f3);
                const float* wr = w1p + (c4 * 4) * T_HID;
                accum64(f0, wr,            h1);
                accum64(f1, wr + T_HID,    h1);
                accum64(f2, wr + 2*T_HID,  h1);
                accum64(f3, wr + 3*T_HID,  h1);
                if (c4 < 19) { a = na; b = nb; c = nc; d = nd; }
            }
        }

        // layer 2
        u64t h2[32];
#pragma unroll
        for (int q = 0; q < 32; q++) h2[q] = ((const u64t*)(sm + SO_B2))[q];
#pragma unroll
        for (int q = 0; q < 32; q++) {
            float a, b; upk2(h1[q], a, b);
            a = fmaxf(a, 0.f); b = fmaxf(b, 0.f);
            accum64(a, sm + SO_W2 + (2 * q) * T_HID,     h2);
            accum64(b, sm + SO_W2 + (2 * q + 1) * T_HID, h2);
        }
        // layer 3 (reuse h1 as h3)
#pragma unroll
        for (int q = 0; q < 32; q++) h1[q] = ((const u64t*)(sm + SO_B3))[q];
#pragma unroll
        for (int q = 0; q < 32; q++) {
            float a, b; upk2(h2[q], a, b);
            a = fmaxf(a, 0.f); b = fmaxf(b, 0.f);
            accum64(a, sm + SO_W3 + (2 * q) * T_HID,     h1);
            accum64(b, sm + SO_W3 + (2 * q + 1) * T_HID, h1);
        }
        // layer 4
        float acc = sm[SO_B4];
#pragma unroll
        for (int q = 0; q < 32; q++) {
            float a, b; upk2(h1[q], a, b);
            acc = fmaf(fmaxf(a, 0.f), sm[SO_W4 + 2 * q],     acc);
            acc = fmaf(fmaxf(b, 0.f), sm[SO_W4 + 2 * q + 1], acc);
        }
        out[g] = acc;
    }
}

// ---------------------------------------------------------------------------
extern "C" void kernel_launch(void* const* d_in, const int* in_sizes, int n_in,
                              void* d_out, int out_size) {
    const float* planes = (const float*)d_in[0];
    const float* coords = (const float*)d_in[1];
    const float* W1 = (const float*)d_in[2];
    const float* b1 = (const float*)d_in[3];
    const float* W2 = (const float*)d_in[4];
    const float* b2 = (const float*)d_in[5];
    const float* W3 = (const float*)d_in[6];
    const float* b3 = (const float*)d_in[7];
    const float* W4 = (const float*)d_in[8];
    const float* b4 = (const float*)d_in[9];
    float* out = (float*)d_out;

    // Kernel A: channel-last transpose of planes into device scratch
    dim3 tg(T_NH * T_NW / 32, (T_NC + 31) / 32, T_NB * T_NP);
    dim3 tb(32, 8);
    transpose_planes_kernel<<<tg, tb>>>(planes);

    // Kernel B: fused sample + MLP (95.2 KB dynamic smem -> 2 CTA/SM)
    size_t smbytes = (size_t)S_FLOATS * sizeof(float);
    cudaFuncSetAttribute(triplane_mlp_kernel,
                         cudaFuncAttributeMaxDynamicSharedMemorySize, (int)smbytes);
    triplane_mlp_kernel<<<296, 128, smbytes>>>(coords, W1, b1, W2, b2, W3, b3,
                                               W4, b4, out);
}

// round 6
// speedup vs baseline: 1.1629x; 1.1629x over previous
#include <cuda_runtime.h>
#include <cuda_bf16.h>
#include <cstdint>

// ---------------- problem constants ----------------
#define T_NB   2
#define T_NP   3
#define T_NC   80
#define T_NH   64
#define T_NW   64
#define T_NM   524288
#define T_NPTS (T_NB * T_NM)      // 1048576
#define N_TILES 8192              // 128 points per tile
#define K1P    248                // layer1 row stride (240 data + 8 pad, never read by MMA)
#define K2P    72                 // layer2/3 row stride (64 data + 8 pad)

// transposed planes scratch: [N*P][H*W][C] fp32
__device__ float g_planes_t[T_NB * T_NP * T_NH * T_NW * T_NC];

// ---------------- smem byte offsets ----------------
#define SM_A1H 0                       // [128][248] bf16 = 63488
#define SM_A1L 63488
#define SM_A2H 0                       // overlay: [128][72] bf16 = 18432
#define SM_A2L 18432
#define SM_B1H 126976                  // [64][248] bf16 = 31744
#define SM_B1L 158720
#define SM_B2H 190464                  // [64][72] bf16 = 9216
#define SM_B2L 199680
#define SM_B3H 208896
#define SM_B3L 218112
#define SM_BIAS 227328                 // floats: [0:64)b1 [64:128)b2 [128:192)b3 [192:256)W4 [256]b4
#define SM_TOTAL 228384

// ---------------- helpers ----------------
static __device__ __forceinline__ uint32_t smem_u32(const void* p) {
    uint32_t a;
    asm("{ .reg .u64 t; cvta.to.shared.u64 t, %1; cvt.u32.u64 %0, t; }" : "=r"(a) : "l"(p));
    return a;
}
static __device__ __forceinline__ uint32_t ldsb32(uint32_t a) {
    uint32_t v;
    asm("ld.shared.b32 %0, [%1];" : "=r"(v) : "r"(a));
    return v;
}
#define LDMX4(r, addr) \
    asm volatile("ldmatrix.sync.aligned.m8n8.x4.shared.b16 {%0,%1,%2,%3}, [%4];" \
        : "=r"((r)[0]), "=r"((r)[1]), "=r"((r)[2]), "=r"((r)[3]) : "r"(addr))
#define MMA_BF16(d, a, b0, b1) \
    asm volatile("mma.sync.aligned.m16n8k16.row.col.f32.bf16.bf16.f32 " \
        "{%0,%1,%2,%3}, {%4,%5,%6,%7}, {%8,%9}, {%0,%1,%2,%3};" \
        : "+f"((d)[0]), "+f"((d)[1]), "+f"((d)[2]), "+f"((d)[3]) \
        : "r"((a)[0]), "r"((a)[1]), "r"((a)[2]), "r"((a)[3]), "r"(b0), "r"(b1))

// split fp32 pair -> packed bf16x2 (hi) + packed bf16x2 (lo residual)
static __device__ __forceinline__ void split2(float f0, float f1, uint32_t& hi, uint32_t& lo) {
    __nv_bfloat16 h0 = __float2bfloat16(f0), h1 = __float2bfloat16(f1);
    __nv_bfloat16 l0 = __float2bfloat16(f0 - __bfloat162float(h0));
    __nv_bfloat16 l1 = __float2bfloat16(f1 - __bfloat162float(h1));
    __nv_bfloat162 H(h0, h1), L(l0, l1);
    hi = *(uint32_t*)&H;
    lo = *(uint32_t*)&L;
}

// ---------------------------------------------------------------------------
// Kernel A: transpose planes [NP][C][HW] -> [NP][HW][C]
// ---------------------------------------------------------------------------
__global__ void transpose_planes_kernel(const float* __restrict__ in) {
    __shared__ float tile[32][33];
    int np = blockIdx.z, hw0 = blockIdx.x * 32, c0 = blockIdx.y * 32;
    const float* src = in + np * (T_NC * T_NH * T_NW);
    float* dst = g_planes_t + np * (T_NH * T_NW * T_NC);
    int hw = hw0 + threadIdx.x;
#pragma unroll
    for (int j = 0; j < 32; j += 8) {
        int c = c0 + threadIdx.y + j;
        if (c < T_NC) tile[threadIdx.y + j][threadIdx.x] = src[c * (T_NH * T_NW) + hw];
    }
    __syncthreads();
    int c = c0 + threadIdx.x;
    if (c < T_NC) {
#pragma unroll
        for (int j = 0; j < 32; j += 8)
            dst[(hw0 + threadIdx.y + j) * T_NC + c] = tile[threadIdx.x][threadIdx.y + j];
    }
}

// ---------------------------------------------------------------------------
// Main fused kernel: gather -> 3x split-bf16 mma.sync GEMM -> dot -> out
// ---------------------------------------------------------------------------
__global__ __launch_bounds__(256, 1)
void triplane_mma_kernel(const float* __restrict__ coords,
                         const float* __restrict__ W1, const float* __restrict__ b1,
                         const float* __restrict__ W2, const float* __restrict__ b2,
                         const float* __restrict__ W3, const float* __restrict__ b3,
                         const float* __restrict__ W4, const float* __restrict__ b4,
                         float* __restrict__ out) {
    extern __shared__ char smb[];
    uint32_t sbase = smem_u32(smb);
    int tid = threadIdx.x, wid = tid >> 5, lane = tid & 31;

    // ---- one-time staging: weights split to bf16 hi/lo ----
    for (int i = tid; i < 240 * 64; i += 256) {           // B1[n][k] = W1[k][n]
        int k = i >> 6, n = i & 63;
        uint32_t hp, lp;
        float w = W1[i];
        split2(w, 0.f, hp, lp);
        *(uint16_t*)(smb + SM_B1H + (n * K1P + k) * 2) = (uint16_t)(hp & 0xFFFF);
        *(uint16_t*)(smb + SM_B1L + (n * K1P + k) * 2) = (uint16_t)(lp & 0xFFFF);
    }
    for (int i = tid; i < 64 * 64; i += 256) {            // B2/B3
        int k = i >> 6, n = i & 63;
        uint32_t hp, lp;
        split2(W2[i], 0.f, hp, lp);
        *(uint16_t*)(smb + SM_B2H + (n * K2P + k) * 2) = (uint16_t)(hp & 0xFFFF);
        *(uint16_t*)(smb + SM_B2L + (n * K2P + k) * 2) = (uint16_t)(lp & 0xFFFF);
        split2(W3[i], 0.f, hp, lp);
        *(uint16_t*)(smb + SM_B3H + (n * K2P + k) * 2) = (uint16_t)(hp & 0xFFFF);
        *(uint16_t*)(smb + SM_B3L + (n * K2P + k) * 2) = (uint16_t)(lp & 0xFFFF);
    }
    float* biasf = (float*)(smb + SM_BIAS);
    if (tid < 64) {
        biasf[tid] = b1[tid];
        biasf[64 + tid] = b2[tid];
        biasf[128 + tid] = b3[tid];
        biasf[192 + tid] = W4[tid];
    }
    if (tid == 0) biasf[256] = b4[0];
    __syncthreads();

    // per-thread invariant fragments/addresses
    const int m0 = wid * 16;
    const int qr = lane >> 2;                 // t/4 (row within 8 / B n-row)
    const int qc = lane & 3;                  // t%4
    const uint32_t aOff1 = sbase + SM_A1H + ((uint32_t)(m0 + (lane & 15)) * K1P + (uint32_t)(lane >> 4) * 8) * 2;
    const uint32_t aOff2 = sbase + SM_A2H + ((uint32_t)(m0 + (lane & 15)) * K2P + (uint32_t)(lane >> 4) * 8) * 2;
    const uint32_t bOff1 = sbase + SM_B1H + ((uint32_t)qr * K1P + (uint32_t)qc * 2) * 2;
    const uint32_t bOff2 = sbase + SM_B2H + ((uint32_t)qr * K2P + (uint32_t)qc * 2) * 2;
    const uint32_t bOff3 = sbase + SM_B3H + ((uint32_t)qr * K2P + (uint32_t)qc * 2) * 2;

    for (int tile = blockIdx.x; tile < N_TILES; tile += gridDim.x) {
        // ---- warp-cooperative gather+blend: 384 (point,plane) jobs ----
        for (int job = wid; job < 384; job += 8) {
            int p = job >> 7, pt = job & 127;
            int gp = tile * 128 + pt;
            int n = gp >> 19;
            float cx = __ldg(coords + 3 * gp);
            float cy = __ldg(coords + 3 * gp + 1);
            float cz = __ldg(coords + 3 * gp + 2);
            float u = (p == 2) ? cz : cx;
            float v = (p == 1) ? cz : cy;
            float gx = fmaf(u, 32.f, 31.5f);
            float gy = fmaf(v, 32.f, 31.5f);
            float x0f = floorf(gx), y0f = floorf(gy);
            float fx = gx - x0f, fy = gy - y0f;
            int x0 = (int)x0f, y0 = (int)y0f;
            int x1 = x0 + 1, y1 = y0 + 1;
            float vx0 = (x0 >= 0 && x0 < 64) ? 1.f : 0.f;
            float vx1 = (x1 >= 0 && x1 < 64) ? 1.f : 0.f;
            float vy0 = (y0 >= 0 && y0 < 64) ? 1.f : 0.f;
            float vy1 = (y1 >= 0 && y1 < 64) ? 1.f : 0.f;
            int xc0 = min(max(x0, 0), 63), xc1 = min(max(x1, 0), 63);
            int yc0 = min(max(y0, 0), 63), yc1 = min(max(y1, 0), 63);
            float wA = (1.f - fx) * (1.f - fy) * vx0 * vy0;
            float wB = fx * (1.f - fy) * vx1 * vy0;
            float wC = (1.f - fx) * fy * vx0 * vy1;
            float wD = fx * fy * vx1 * vy1;

            const float* plane = g_planes_t + (size_t)((n * 3 + p) * 4096) * 80;
            const float2* pA = (const float2*)(plane + (yc0 * 64 + xc0) * 80);
            const float2* pB = (const float2*)(plane + (yc0 * 64 + xc1) * 80);
            const float2* pC = (const float2*)(plane + (yc1 * 64 + xc0) * 80);
            const float2* pD = (const float2*)(plane + (yc1 * 64 + xc1) * 80);

            int q1 = 32 + (lane & 7);
            float2 A0 = __ldg(pA + lane), B0 = __ldg(pB + lane);
            float2 C0 = __ldg(pC + lane), D0 = __ldg(pD + lane);
            float2 A1 = __ldg(pA + q1), B1v = __ldg(pB + q1);
            float2 C1 = __ldg(pC + q1), D1v = __ldg(pD + q1);

            float f0 = fmaf(wA, A0.x, fmaf(wB, B0.x, fmaf(wC, C0.x, wD * D0.x)));
            float f1 = fmaf(wA, A0.y, fmaf(wB, B0.y, fmaf(wC, C0.y, wD * D0.y)));
            uint32_t hp, lp;
            split2(f0, f1, hp, lp);
            uint32_t off = (uint32_t)pt * (K1P * 2) + (uint32_t)(p * 80 + 2 * lane) * 2;
            *(uint32_t*)(smb + SM_A1H + off) = hp;
            *(uint32_t*)(smb + SM_A1L + off) = lp;
            if (lane < 8) {
                float g0 = fmaf(wA, A1.x, fmaf(wB, B1v.x, fmaf(wC, C1.x, wD * D1v.x)));
                float g1 = fmaf(wA, A1.y, fmaf(wB, B1v.y, fmaf(wC, C1.y, wD * D1v.y)));
                split2(g0, g1, hp, lp);
                uint32_t off2 = (uint32_t)pt * (K1P * 2) + (uint32_t)(p * 80 + 64 + 2 * lane) * 2;
                *(uint32_t*)(smb + SM_A1H + off2) = hp;
                *(uint32_t*)(smb + SM_A1L + off2) = lp;
            }
        }
        __syncthreads();

        // ---- layer 1: [128x240] @ [240x64], 3-pass split-bf16 ----
        // K = 240 = EXACTLY 15 k-tiles of 16 (kt<15; pad cols never touched).
        float d[8][4];
#pragma unroll
        for (int nt = 0; nt < 8; nt++)
#pragma unroll
            for (int j = 0; j < 4; j++) d[nt][j] = 0.f;
#pragma unroll 3
        for (int kt = 0; kt < 15; kt++) {
            uint32_t ah[4], al[4];
            LDMX4(ah, aOff1 + kt * 32);
            LDMX4(al, aOff1 + (SM_A1L - SM_A1H) + kt * 32);
#pragma unroll
            for (int nt = 0; nt < 8; nt++) {
                uint32_t bb = bOff1 + nt * (8 * K1P * 2) + kt * 32;
                uint32_t bh0 = ldsb32(bb), bh1 = ldsb32(bb + 16);
                uint32_t bl0 = ldsb32(bb + (SM_B1L - SM_B1H));
                uint32_t bl1 = ldsb32(bb + (SM_B1L - SM_B1H) + 16);
                MMA_BF16(d[nt], ah, bh0, bh1);
                MMA_BF16(d[nt], al, bh0, bh1);
                MMA_BF16(d[nt], ah, bl0, bl1);
            }
        }
        __syncthreads();
        // epilogue 1: bias+relu, split, store A2
        {
            int rlo = m0 + qr, rhi = rlo + 8, nb = qc * 2;
#pragma unroll
            for (int nt = 0; nt < 8; nt++) {
                int n = nt * 8 + nb;
                float f0 = fmaxf(d[nt][0] + biasf[n], 0.f);
                float f1 = fmaxf(d[nt][1] + biasf[n + 1], 0.f);
                float f2 = fmaxf(d[nt][2] + biasf[n], 0.f);
                float f3 = fmaxf(d[nt][3] + biasf[n + 1], 0.f);
                uint32_t hp, lp;
                split2(f0, f1, hp, lp);
                uint32_t o = (uint32_t)(rlo * K2P + n) * 2;
                *(uint32_t*)(smb + SM_A2H + o) = hp;
                *(uint32_t*)(smb + SM_A2L + o) = lp;
                split2(f2, f3, hp, lp);
                o = (uint32_t)(rhi * K2P + n) * 2;
                *(uint32_t*)(smb + SM_A2H + o) = hp;
                *(uint32_t*)(smb + SM_A2L + o) = lp;
            }
        }
        __syncthreads();

        // ---- layer 2 (K=64 = 4 k-tiles exactly) ----
#pragma unroll
        for (int nt = 0; nt < 8; nt++)
#pragma unroll
            for (int j = 0; j < 4; j++) d[nt][j] = 0.f;
#pragma unroll
        for (int kt = 0; kt < 4; kt++) {
            uint32_t ah[4], al[4];
            LDMX4(ah, aOff2 + kt * 32);
            LDMX4(al, aOff2 + (SM_A2L - SM_A2H) + kt * 32);
#pragma unroll
            for (int nt = 0; nt < 8; nt++) {
                uint32_t bb = bOff2 + nt * (8 * K2P * 2) + kt * 32;
                uint32_t bh0 = ldsb32(bb), bh1 = ldsb32(bb + 16);
                uint32_t bl0 = ldsb32(bb + (SM_B2L - SM_B2H));
                uint32_t bl1 = ldsb32(bb + (SM_B2L - SM_B2H) + 16);
                MMA_BF16(d[nt], ah, bh0, bh1);
                MMA_BF16(d[nt], al, bh0, bh1);
                MMA_BF16(d[nt], ah, bl0, bl1);
            }
        }
        __syncthreads();
        // epilogue 2
        {
            int rlo = m0 + qr, rhi = rlo + 8, nb = qc * 2;
#pragma unroll
            for (int nt = 0; nt < 8; nt++) {
                int n = nt * 8 + nb;
                float f0 = fmaxf(d[nt][0] + biasf[64 + n], 0.f);
                float f1 = fmaxf(d[nt][1] + biasf[64 + n + 1], 0.f);
                float f2 = fmaxf(d[nt][2] + biasf[64 + n], 0.f);
                float f3 = fmaxf(d[nt][3] + biasf[64 + n + 1], 0.f);
                uint32_t hp, lp;
                split2(f0, f1, hp, lp);
                uint32_t o = (uint32_t)(rlo * K2P + n) * 2;
                *(uint32_t*)(smb + SM_A2H + o) = hp;
                *(uint32_t*)(smb + SM_A2L + o) = lp;
                split2(f2, f3, hp, lp);
                o = (uint32_t)(rhi * K2P + n) * 2;
                *(uint32_t*)(smb + SM_A2H + o) = hp;
                *(uint32_t*)(smb + SM_A2L + o) = lp;
            }
        }
        __syncthreads();

        // ---- layer 3 ----
#pragma unroll
        for (int nt = 0; nt < 8; nt++)
#pragma unroll
            for (int j = 0; j < 4; j++) d[nt][j] = 0.f;
#pragma unroll
        for (int kt = 0; kt < 4; kt++) {
            uint32_t ah[4], al[4];
            LDMX4(ah, aOff2 + kt * 32);
            LDMX4(al, aOff2 + (SM_A2L - SM_A2H) + kt * 32);
#pragma unroll
            for (int nt = 0; nt < 8; nt++) {
                uint32_t bb = bOff3 + nt * (8 * K2P * 2) + kt * 32;
                uint32_t bh0 = ldsb32(bb), bh1 = ldsb32(bb + 16);
                uint32_t bl0 = ldsb32(bb + (SM_B3L - SM_B3H));
                uint32_t bl1 = ldsb32(bb + (SM_B3L - SM_B3H) + 16);
                MMA_BF16(d[nt], ah, bh0, bh1);
                MMA_BF16(d[nt], al, bh0, bh1);
                MMA_BF16(d[nt], ah, bl0, bl1);
            }
        }
        __syncthreads();   // A2 reads done; next gather may overwrite

        // ---- layer 4: relu + dot(W4) + b4 (registers + shuffle) ----
        {
            int nb = qc * 2;
            float accLo = 0.f, accHi = 0.f;
#pragma unroll
            for (int nt = 0; nt < 8; nt++) {
                int n = nt * 8 + nb;
                accLo = fmaf(fmaxf(d[nt][0] + biasf[128 + n], 0.f),     biasf[192 + n],     accLo);
                accLo = fmaf(fmaxf(d[nt][1] + biasf[128 + n + 1], 0.f), biasf[192 + n + 1], accLo);
                accHi = fmaf(fmaxf(d[nt][2] + biasf[128 + n], 0.f),     biasf[192 + n],     accHi);
                accHi = fmaf(fmaxf(d[nt][3] + biasf[128 + n + 1], 0.f), biasf[192 + n + 1], accHi);
            }
            accLo += __shfl_xor_sync(0xFFFFFFFF, accLo, 1);
            accLo += __shfl_xor_sync(0xFFFFFFFF, accLo, 2);
            accHi += __shfl_xor_sync(0xFFFFFFFF, accHi, 1);
            accHi += __shfl_xor_sync(0xFFFFFFFF, accHi, 2);
            if (qc == 0) {
                int base = tile * 128 + m0 + qr;
                out[base] = accLo + biasf[256];
                out[base + 8] = accHi + biasf[256];
            }
        }
    }
}

// ---------------------------------------------------------------------------
extern "C" void kernel_launch(void* const* d_in, const int* in_sizes, int n_in,
                              void* d_out, int out_size) {
    const float* planes = (const float*)d_in[0];
    const float* coords = (const float*)d_in[1];
    const float* W1 = (const float*)d_in[2];
    const float* b1 = (const float*)d_in[3];
    const float* W2 = (const float*)d_in[4];
    const float* b2 = (const float*)d_in[5];
    const float* W3 = (const float*)d_in[6];
    const float* b3 = (const float*)d_in[7];
    const float* W4 = (const float*)d_in[8];
    const float* b4 = (const float*)d_in[9];
    float* out = (float*)d_out;

    dim3 tg(T_NH * T_NW / 32, (T_NC + 31) / 32, T_NB * T_NP);
    transpose_planes_kernel<<<tg, dim3(32, 8)>>>(planes);

    cudaFuncSetAttribute(triplane_mma_kernel,
                         cudaFuncAttributeMaxDynamicSharedMemorySize, SM_TOTAL);
    triplane_mma_kernel<<<148, 256, SM_TOTAL>>>(coords, W1, b1, W2, b2, W3, b3,
                                                W4, b4, out);
}

// round 8
// speedup vs baseline: 3.3195x; 2.8545x over previous
#include <cuda_runtime.h>
#include <cuda_fp16.h>
#include <cstdint>

// ---------------- problem constants ----------------
#define T_NB   2
#define T_NP   3
#define T_NC   80
#define T_NH   64
#define T_NW   64
#define T_NM   524288
#define T_NPTS (T_NB * T_NM)      // 1048576
#define N_TILES 8192              // 128 points per tile
#define K1P    248                // layer1 row stride (240 data + 8 pad), 496B = 31x16B (odd)
#define K2P    72                 // layer2/3 row stride (64 + 8), 144B = 9x16B (odd)

// transposed planes scratch: [N*P][H*W][C] fp32
__device__ float g_planes_t[T_NB * T_NP * T_NH * T_NW * T_NC];

// ---------------- smem byte offsets (fp16 single-plane) ----------------
#define SM_A1  0                       // [128][248] f16 = 63488
#define SM_A2  0                       // overlay: [128][72] f16 = 18432
#define SM_B1  63488                   // [64][248] f16 = 31744
#define SM_B2  95232                   // [64][72] f16 = 9216
#define SM_B3  104448                  // [64][72] f16 = 9216
#define SM_BIAS 113664                 // floats: [0:64)b1 [64:128)b2 [128:192)b3 [192:256)W4 [256]b4
#define SM_TOTAL 114692                // 112.0 KiB -> 2 CTAs/SM

// ---------------- helpers ----------------
static __device__ __forceinline__ uint32_t smem_u32(const void* p) {
    uint32_t a;
    asm("{ .reg .u64 t; cvta.to.shared.u64 t, %1; cvt.u32.u64 %0, t; }" : "=r"(a) : "l"(p));
    return a;
}
static __device__ __forceinline__ uint32_t ldsb32(uint32_t a) {
    uint32_t v;
    asm("ld.shared.b32 %0, [%1];" : "=r"(v) : "r"(a));
    return v;
}
#define LDMX4(r, addr) \
    asm volatile("ldmatrix.sync.aligned.m8n8.x4.shared.b16 {%0,%1,%2,%3}, [%4];" \
        : "=r"((r)[0]), "=r"((r)[1]), "=r"((r)[2]), "=r"((r)[3]) : "r"(addr))
#define MMA_F16(d, a, b0, b1) \
    asm volatile("mma.sync.aligned.m16n8k16.row.col.f32.f16.f16.f32 " \
        "{%0,%1,%2,%3}, {%4,%5,%6,%7}, {%8,%9}, {%0,%1,%2,%3};" \
        : "+f"((d)[0]), "+f"((d)[1]), "+f"((d)[2]), "+f"((d)[3]) \
        : "r"((a)[0]), "r"((a)[1]), "r"((a)[2]), "r"((a)[3]), "r"(b0), "r"(b1))

static __device__ __forceinline__ uint32_t pack_h2(float f0, float f1) {
    __half2 h = __floats2half2_rn(f0, f1);
    return *(uint32_t*)&h;
}

// ---------------------------------------------------------------------------
// Kernel A: transpose planes [NP][C][HW] -> [NP][HW][C]
// ---------------------------------------------------------------------------
__global__ void transpose_planes_kernel(const float* __restrict__ in) {
    __shared__ float tile[32][33];
    int np = blockIdx.z, hw0 = blockIdx.x * 32, c0 = blockIdx.y * 32;
    const float* src = in + np * (T_NC * T_NH * T_NW);
    float* dst = g_planes_t + np * (T_NH * T_NW * T_NC);
    int hw = hw0 + threadIdx.x;
#pragma unroll
    for (int j = 0; j < 32; j += 8) {
        int c = c0 + threadIdx.y + j;
        if (c < T_NC) tile[threadIdx.y + j][threadIdx.x] = src[c * (T_NH * T_NW) + hw];
    }
    __syncthreads();
    int c = c0 + threadIdx.x;
    if (c < T_NC) {
#pragma unroll
        for (int j = 0; j < 32; j += 8)
            dst[(hw0 + threadIdx.y + j) * T_NC + c] = tile[threadIdx.x][threadIdx.y + j];
    }
}

// ---------------------------------------------------------------------------
// Main fused kernel: gather -> 3x fp16 mma.sync GEMM -> dot -> out
// 2 CTAs/SM for latency overlap (gather of one CTA hides under MMA of other)
// ---------------------------------------------------------------------------
__global__ __launch_bounds__(256, 2)
void triplane_mma_kernel(const float* __restrict__ coords,
                         const float* __restrict__ W1, const float* __restrict__ b1,
                         const float* __restrict__ W2, const float* __restrict__ b2,
                         const float* __restrict__ W3, const float* __restrict__ b3,
                         const float* __restrict__ W4, const float* __restrict__ b4,
                         float* __restrict__ out) {
    extern __shared__ char smb[];
    uint32_t sbase = smem_u32(smb);
    int tid = threadIdx.x, wid = tid >> 5, lane = tid & 31;

    // ---- one-time staging: weights -> fp16 smem ----
    for (int i = tid; i < 240 * 64; i += 256) {           // B1[n][k] = W1[k][n]
        int k = i >> 6, n = i & 63;
        *(__half*)(smb + SM_B1 + (n * K1P + k) * 2) = __float2half_rn(W1[i]);
    }
    for (int i = tid; i < 64 * 64; i += 256) {            // B2/B3
        int k = i >> 6, n = i & 63;
        *(__half*)(smb + SM_B2 + (n * K2P + k) * 2) = __float2half_rn(W2[i]);
        *(__half*)(smb + SM_B3 + (n * K2P + k) * 2) = __float2half_rn(W3[i]);
    }
    float* biasf = (float*)(smb + SM_BIAS);
    if (tid < 64) {
        biasf[tid] = b1[tid];
        biasf[64 + tid] = b2[tid];
        biasf[128 + tid] = b3[tid];
        biasf[192 + tid] = W4[tid];
    }
    if (tid == 0) biasf[256] = b4[0];
    __syncthreads();

    // per-thread invariant fragment addresses
    const int m0 = wid * 16;
    const int qr = lane >> 2;                 // B n-row / acc row-in-8
    const int qc = lane & 3;
    const uint32_t aOff1 = sbase + SM_A1 + ((uint32_t)(m0 + (lane & 15)) * K1P + (uint32_t)(lane >> 4) * 8) * 2;
    const uint32_t aOff2 = sbase + SM_A2 + ((uint32_t)(m0 + (lane & 15)) * K2P + (uint32_t)(lane >> 4) * 8) * 2;
    const uint32_t bOff1 = sbase + SM_B1 + ((uint32_t)qr * K1P + (uint32_t)qc * 2) * 2;
    const uint32_t bOff2 = sbase + SM_B2 + ((uint32_t)qr * K2P + (uint32_t)qc * 2) * 2;
    const uint32_t bOff3 = sbase + SM_B3 + ((uint32_t)qr * K2P + (uint32_t)qc * 2) * 2;

    for (int tile = blockIdx.x; tile < N_TILES; tile += gridDim.x) {
        // ---- warp-cooperative gather+blend: 384 (point,plane) jobs ----
#pragma unroll 2
        for (int job = wid; job < 384; job += 8) {
            int p = job >> 7, pt = job & 127;
            int gp = tile * 128 + pt;
            int n = gp >> 19;
            float cx = __ldg(coords + 3 * gp);
            float cy = __ldg(coords + 3 * gp + 1);
            float cz = __ldg(coords + 3 * gp + 2);
            float u = (p == 2) ? cz : cx;
            float v = (p == 1) ? cz : cy;
            float gx = fmaf(u, 32.f, 31.5f);
            float gy = fmaf(v, 32.f, 31.5f);
            float x0f = floorf(gx), y0f = floorf(gy);
            float fx = gx - x0f, fy = gy - y0f;
            int x0 = (int)x0f, y0 = (int)y0f;
            int x1 = x0 + 1, y1 = y0 + 1;
            float vx0 = (x0 >= 0 && x0 < 64) ? 1.f : 0.f;
            float vx1 = (x1 >= 0 && x1 < 64) ? 1.f : 0.f;
            float vy0 = (y0 >= 0 && y0 < 64) ? 1.f : 0.f;
            float vy1 = (y1 >= 0 && y1 < 64) ? 1.f : 0.f;
            int xc0 = min(max(x0, 0), 63), xc1 = min(max(x1, 0), 63);
            int yc0 = min(max(y0, 0), 63), yc1 = min(max(y1, 0), 63);
            float wA = (1.f - fx) * (1.f - fy) * vx0 * vy0;
            float wB = fx * (1.f - fy) * vx1 * vy0;
            float wC = (1.f - fx) * fy * vx0 * vy1;
            float wD = fx * fy * vx1 * vy1;

            const float* plane = g_planes_t + (size_t)((n * 3 + p) * 4096) * 80;
            const float2* pA = (const float2*)(plane + (yc0 * 64 + xc0) * 80);
            const float2* pB = (const float2*)(plane + (yc0 * 64 + xc1) * 80);
            const float2* pC = (const float2*)(plane + (yc1 * 64 + xc0) * 80);
            const float2* pD = (const float2*)(plane + (yc1 * 64 + xc1) * 80);

            int q1 = 32 + (lane & 7);
            float2 A0 = __ldg(pA + lane), B0 = __ldg(pB + lane);
            float2 C0 = __ldg(pC + lane), D0 = __ldg(pD + lane);
            float2 A1 = __ldg(pA + q1), B1v = __ldg(pB + q1);
            float2 C1 = __ldg(pC + q1), D1v = __ldg(pD + q1);

            float f0 = fmaf(wA, A0.x, fmaf(wB, B0.x, fmaf(wC, C0.x, wD * D0.x)));
            float f1 = fmaf(wA, A0.y, fmaf(wB, B0.y, fmaf(wC, C0.y, wD * D0.y)));
            uint32_t off = (uint32_t)pt * (K1P * 2) + (uint32_t)(p * 80 + 2 * lane) * 2;
            *(uint32_t*)(smb + SM_A1 + off) = pack_h2(f0, f1);
            if (lane < 8) {
                float g0 = fmaf(wA, A1.x, fmaf(wB, B1v.x, fmaf(wC, C1.x, wD * D1v.x)));
                float g1 = fmaf(wA, A1.y, fmaf(wB, B1v.y, fmaf(wC, C1.y, wD * D1v.y)));
                uint32_t off2 = (uint32_t)pt * (K1P * 2) + (uint32_t)(p * 80 + 64 + 2 * lane) * 2;
                *(uint32_t*)(smb + SM_A1 + off2) = pack_h2(g0, g1);
            }
        }
        __syncthreads();

        // ---- layer 1: [128x240] @ [240x64]; K = exactly 15 k-tiles ----
        float d[8][4];
#pragma unroll
        for (int nt = 0; nt < 8; nt++)
#pragma unroll
            for (int j = 0; j < 4; j++) d[nt][j] = 0.f;
#pragma unroll 3
        for (int kt = 0; kt < 15; kt++) {
            uint32_t ah[4];
            LDMX4(ah, aOff1 + kt * 32);
#pragma unroll
            for (int nt = 0; nt < 8; nt++) {
                uint32_t bb = bOff1 + nt * (8 * K1P * 2) + kt * 32;
                uint32_t bh0 = ldsb32(bb), bh1 = ldsb32(bb + 16);
                MMA_F16(d[nt], ah, bh0, bh1);
            }
        }
        __syncthreads();
        // epilogue 1: bias+relu -> fp16 A2
        {
            int rlo = m0 + qr, rhi = rlo + 8, nb = qc * 2;
#pragma unroll
            for (int nt = 0; nt < 8; nt++) {
                int n = nt * 8 + nb;
                float f0 = fmaxf(d[nt][0] + biasf[n], 0.f);
                float f1 = fmaxf(d[nt][1] + biasf[n + 1], 0.f);
                float f2 = fmaxf(d[nt][2] + biasf[n], 0.f);
                float f3 = fmaxf(d[nt][3] + biasf[n + 1], 0.f);
                *(uint32_t*)(smb + SM_A2 + (uint32_t)(rlo * K2P + n) * 2) = pack_h2(f0, f1);
                *(uint32_t*)(smb + SM_A2 + (uint32_t)(rhi * K2P + n) * 2) = pack_h2(f2, f3);
            }
        }
        __syncthreads();

        // ---- layer 2 (K=64 = 4 k-tiles) ----
#pragma unroll
        for (int nt = 0; nt < 8; nt++)
#pragma unroll
            for (int j = 0; j < 4; j++) d[nt][j] = 0.f;
#pragma unroll
        for (int kt = 0; kt < 4; kt++) {
            uint32_t ah[4];
            LDMX4(ah, aOff2 + kt * 32);
#pragma unroll
            for (int nt = 0; nt < 8; nt++) {
                uint32_t bb = bOff2 + nt * (8 * K2P * 2) + kt * 32;
                uint32_t bh0 = ldsb32(bb), bh1 = ldsb32(bb + 16);
                MMA_F16(d[nt], ah, bh0, bh1);
            }
        }
        __syncthreads();
        // epilogue 2
        {
            int rlo = m0 + qr, rhi = rlo + 8, nb = qc * 2;
#pragma unroll
            for (int nt = 0; nt < 8; nt++) {
                int n = nt * 8 + nb;
                float f0 = fmaxf(d[nt][0] + biasf[64 + n], 0.f);
                float f1 = fmaxf(d[nt][1] + biasf[64 + n + 1], 0.f);
                float f2 = fmaxf(d[nt][2] + biasf[64 + n], 0.f);
                float f3 = fmaxf(d[nt][3] + biasf[64 + n + 1], 0.f);
                *(uint32_t*)(smb + SM_A2 + (uint32_t)(rlo * K2P + n) * 2) = pack_h2(f0, f1);
                *(uint32_t*)(smb + SM_A2 + (uint32_t)(rhi * K2P + n) * 2) = pack_h2(f2, f3);
            }
        }
        __syncthreads();

        // ---- layer 3 ----
#pragma unroll
        for (int nt = 0; nt < 8; nt++)
#pragma unroll
            for (int j = 0; j < 4; j++) d[nt][j] = 0.f;
#pragma unroll
        for (int kt = 0; kt < 4; kt++) {
            uint32_t ah[4];
            LDMX4(ah, aOff2 + kt * 32);
#pragma unroll
            for (int nt = 0; nt < 8; nt++) {
                uint32_t bb = bOff3 + nt * (8 * K2P * 2) + kt * 32;
                uint32_t bh0 = ldsb32(bb), bh1 = ldsb32(bb + 16);
                MMA_F16(d[nt], ah, bh0, bh1);
            }
        }
        __syncthreads();   // A2 reads done; next gather may overwrite A1/A2

        // ---- layer 4: relu + dot(W4) + b4 (registers + shuffle) ----
        {
            int nb = qc * 2;
            float accLo = 0.f, accHi = 0.f;
#pragma unroll
            for (int nt = 0; nt < 8; nt++) {
                int n = nt * 8 + nb;
                accLo = fmaf(fmaxf(d[nt][0] + biasf[128 + n], 0.f),     biasf[192 + n],     accLo);
                accLo = fmaf(fmaxf(d[nt][1] + biasf[128 + n + 1], 0.f), biasf[192 + n + 1], accLo);
                accHi = fmaf(fmaxf(d[nt][2] + biasf[128 + n], 0.f),     biasf[192 + n],     accHi);
                accHi = fmaf(fmaxf(d[nt][3] + biasf[128 + n + 1], 0.f), biasf[192 + n + 1], accHi);
            }
            accLo += __shfl_xor_sync(0xFFFFFFFF, accLo, 1);
            accLo += __shfl_xor_sync(0xFFFFFFFF, accLo, 2);
            accHi += __shfl_xor_sync(0xFFFFFFFF, accHi, 1);
            accHi += __shfl_xor_sync(0xFFFFFFFF, accHi, 2);
            if (qc == 0) {
                int base = tile * 128 + m0 + qr;
                out[base] = accLo + biasf[256];
                out[base + 8] = accHi + biasf[256];
            }
        }
    }
}

// ---------------------------------------------------------------------------
extern "C" void kernel_launch(void* const* d_in, const int* in_sizes, int n_in,
                              void* d_out, int out_size) {
    const float* planes = (const float*)d_in[0];
    const float* coords = (const float*)d_in[1];
    const float* W1 = (const float*)d_in[2];
    const float* b1 = (const float*)d_in[3];
    const float* W2 = (const float*)d_in[4];
    const float* b2 = (const float*)d_in[5];
    const float* W3 = (const float*)d_in[6];
    const float* b3 = (const float*)d_in[7];
    const float* W4 = (const float*)d_in[8];
    const float* b4 = (const float*)d_in[9];
    float* out = (float*)d_out;

    dim3 tg(T_NH * T_NW / 32, (T_NC + 31) / 32, T_NB * T_NP);
    transpose_planes_kernel<<<tg, dim3(32, 8)>>>(planes);

    cudaFuncSetAttribute(triplane_mma_kernel,
                         cudaFuncAttributeMaxDynamicSharedMemorySize, SM_TOTAL);
    triplane_mma_kernel<<<296, 256, SM_TOTAL>>>(coords, W1, b1, W2, b2, W3, b3,
                                                W4, b4, out);
}

// round 10
// speedup vs baseline: 3.5158x; 1.0591x over previous
#include <cuda_runtime.h>
#include <cuda_fp16.h>
#include <cstdint>

// ---------------- problem constants ----------------
#define T_NB   2
#define T_NP   3
#define T_NC   80
#define T_NH   64
#define T_NW   64
#define T_NM   524288
#define T_NPTS (T_NB * T_NM)      // 1048576
#define N_TILES 8192              // 128 points per tile
#define K1P    248                // layer1 A row stride (240 data + 8 pad), 496B = 31x16B (odd)
#define K2P    72                 // layer2/3 B row stride (64 + 8), 144B = 9x16B (odd)

// transposed planes scratch: [N*P][H*W][C] fp32
__device__ float g_planes_t[T_NB * T_NP * T_NH * T_NW * T_NC];

// ---------------- smem byte offsets ----------------
#define SM_A1  0                       // [128][248] f16 = 63488
#define SM_B1  63488                   // [64][248] f16 = 31744
#define SM_B2  95232                   // [64][72] f16 = 9216
#define SM_B3  104448                  // [64][72] f16 = 9216
#define SM_BIAS 113664                 // floats: [0:64)b1 [64:128)b2 [128:192)b3 [192:256)W4 [256]b4
#define SM_TOTAL 114692                // 112.0 KiB -> 2 CTAs/SM

// ---------------- helpers ----------------
static __device__ __forceinline__ uint32_t smem_u32(const void* p) {
    uint32_t a;
    asm("{ .reg .u64 t; cvta.to.shared.u64 t, %1; cvt.u32.u64 %0, t; }" : "=r"(a) : "l"(p));
    return a;
}
static __device__ __forceinline__ uint32_t ldsb32(uint32_t a) {
    uint32_t v;
    asm("ld.shared.b32 %0, [%1];" : "=r"(v) : "r"(a));
    return v;
}
#define LDMX4(r, addr) \
    asm volatile("ldmatrix.sync.aligned.m8n8.x4.shared.b16 {%0,%1,%2,%3}, [%4];" \
        : "=r"((r)[0]), "=r"((r)[1]), "=r"((r)[2]), "=r"((r)[3]) : "r"(addr))
#define MMA_F16(d, a, b0, b1) \
    asm volatile("mma.sync.aligned.m16n8k16.row.col.f32.f16.f16.f32 " \
        "{%0,%1,%2,%3}, {%4,%5,%6,%7}, {%8,%9}, {%0,%1,%2,%3};" \
        : "+f"((d)[0]), "+f"((d)[1]), "+f"((d)[2]), "+f"((d)[3]) \
        : "r"((a)[0]), "r"((a)[1]), "r"((a)[2]), "r"((a)[3]), "r"(b0), "r"(b1))

static __device__ __forceinline__ uint32_t pack_h2(float f0, float f1) {
    __half2 h = __floats2half2_rn(f0, f1);
    return *(uint32_t*)&h;
}

// ---------------------------------------------------------------------------
// Kernel A: transpose planes [NP][C][HW] -> [NP][HW][C]
// ---------------------------------------------------------------------------
__global__ void transpose_planes_kernel(const float* __restrict__ in) {
    __shared__ float tile[32][33];
    int np = blockIdx.z, hw0 = blockIdx.x * 32, c0 = blockIdx.y * 32;
    const float* src = in + np * (T_NC * T_NH * T_NW);
    float* dst = g_planes_t + np * (T_NH * T_NW * T_NC);
    int hw = hw0 + threadIdx.x;
#pragma unroll
    for (int j = 0; j < 32; j += 8) {
        int c = c0 + threadIdx.y + j;
        if (c < T_NC) tile[threadIdx.y + j][threadIdx.x] = src[c * (T_NH * T_NW) + hw];
    }
    __syncthreads();
    int c = c0 + threadIdx.x;
    if (c < T_NC) {
#pragma unroll
        for (int j = 0; j < 32; j += 8)
            dst[(hw0 + threadIdx.y + j) * T_NC + c] = tile[threadIdx.x][threadIdx.y + j];
    }
}

// ---------------------------------------------------------------------------
// Main fused kernel: gather -> layer1 MMA (smem A) -> layers 2/3/4 fully in
// registers (accumulator fragment == next A fragment layout; no smem bounce).
// Only 2 __syncthreads per tile (both protecting the shared A1 buffer).
// ---------------------------------------------------------------------------
__global__ __launch_bounds__(256, 2)
void triplane_mma_kernel(const float* __restrict__ coords,
                         const float* __restrict__ W1, const float* __restrict__ b1,
                         const float* __restrict__ W2, const float* __restrict__ b2,
                         const float* __restrict__ W3, const float* __restrict__ b3,
                         const float* __restrict__ W4, const float* __restrict__ b4,
                         float* __restrict__ out) {
    extern __shared__ char smb[];
    uint32_t sbase = smem_u32(smb);
    int tid = threadIdx.x, wid = tid >> 5, lane = tid & 31;

    // ---- one-time staging: weights -> fp16 smem ----
    for (int i = tid; i < 240 * 64; i += 256) {           // B1[n][k] = W1[k][n]
        int k = i >> 6, n = i & 63;
        *(__half*)(smb + SM_B1 + (n * K1P + k) * 2) = __float2half_rn(W1[i]);
    }
    for (int i = tid; i < 64 * 64; i += 256) {            // B2/B3
        int k = i >> 6, n = i & 63;
        *(__half*)(smb + SM_B2 + (n * K2P + k) * 2) = __float2half_rn(W2[i]);
        *(__half*)(smb + SM_B3 + (n * K2P + k) * 2) = __float2half_rn(W3[i]);
    }
    float* biasf = (float*)(smb + SM_BIAS);
    if (tid < 64) {
        biasf[tid] = b1[tid];
        biasf[64 + tid] = b2[tid];
        biasf[128 + tid] = b3[tid];
        biasf[192 + tid] = W4[tid];
    }
    if (tid == 0) biasf[256] = b4[0];
    __syncthreads();

    // per-thread invariant fragment addresses
    const int m0 = wid * 16;
    const int qr = lane >> 2;                 // acc row-in-8 / B n-row
    const int qc = lane & 3;
    const uint32_t aOff1 = sbase + SM_A1 + ((uint32_t)(m0 + (lane & 15)) * K1P + (uint32_t)(lane >> 4) * 8) * 2;
    const uint32_t bOff1 = sbase + SM_B1 + ((uint32_t)qr * K1P + (uint32_t)qc * 2) * 2;
    const uint32_t bOff2 = sbase + SM_B2 + ((uint32_t)qr * K2P + (uint32_t)qc * 2) * 2;
    const uint32_t bOff3 = sbase + SM_B3 + ((uint32_t)qr * K2P + (uint32_t)qc * 2) * 2;
    const int nb = qc * 2;                    // acc col offset within n-tile

    for (int tile = blockIdx.x; tile < N_TILES; tile += gridDim.x) {
        // ---- warp-cooperative gather+blend: 384 (point,plane) jobs ----
#pragma unroll 2
        for (int job = wid; job < 384; job += 8) {
            int p = job >> 7, pt = job & 127;
            int gp = tile * 128 + pt;
            int n = gp >> 19;
            float cx = __ldg(coords + 3 * gp);
            float cy = __ldg(coords + 3 * gp + 1);
            float cz = __ldg(coords + 3 * gp + 2);
            float u = (p == 2) ? cz : cx;
            float v = (p == 1) ? cz : cy;
            float gx = fmaf(u, 32.f, 31.5f);
            float gy = fmaf(v, 32.f, 31.5f);
            float x0f = floorf(gx), y0f = floorf(gy);
            float fx = gx - x0f, fy = gy - y0f;
            int x0 = (int)x0f, y0 = (int)y0f;
            int x1 = x0 + 1, y1 = y0 + 1;
            float vx0 = (x0 >= 0 && x0 < 64) ? 1.f : 0.f;
            float vx1 = (x1 >= 0 && x1 < 64) ? 1.f : 0.f;
            float vy0 = (y0 >= 0 && y0 < 64) ? 1.f : 0.f;
            float vy1 = (y1 >= 0 && y1 < 64) ? 1.f : 0.f;
            int xc0 = min(max(x0, 0), 63), xc1 = min(max(x1, 0), 63);
            int yc0 = min(max(y0, 0), 63), yc1 = min(max(y1, 0), 63);
            float wA = (1.f - fx) * (1.f - fy) * vx0 * vy0;
            float wB = fx * (1.f - fy) * vx1 * vy0;
            float wC = (1.f - fx) * fy * vx0 * vy1;
            float wD = fx * fy * vx1 * vy1;

            const float* plane = g_planes_t + (size_t)((n * 3 + p) * 4096) * 80;
            const float2* pA = (const float2*)(plane + (yc0 * 64 + xc0) * 80);
            const float2* pB = (const float2*)(plane + (yc0 * 64 + xc1) * 80);
            const float2* pC = (const float2*)(plane + (yc1 * 64 + xc0) * 80);
            const float2* pD = (const float2*)(plane + (yc1 * 64 + xc1) * 80);

            int q1 = 32 + (lane & 7);
            float2 A0 = __ldg(pA + lane), B0 = __ldg(pB + lane);
            float2 C0 = __ldg(pC + lane), D0 = __ldg(pD + lane);
            float2 A1 = __ldg(pA + q1), B1v = __ldg(pB + q1);
            float2 C1 = __ldg(pC + q1), D1v = __ldg(pD + q1);

            float f0 = fmaf(wA, A0.x, fmaf(wB, B0.x, fmaf(wC, C0.x, wD * D0.x)));
            float f1 = fmaf(wA, A0.y, fmaf(wB, B0.y, fmaf(wC, C0.y, wD * D0.y)));
            uint32_t off = (uint32_t)pt * (K1P * 2) + (uint32_t)(p * 80 + 2 * lane) * 2;
            *(uint32_t*)(smb + SM_A1 + off) = pack_h2(f0, f1);
            if (lane < 8) {
                float g0 = fmaf(wA, A1.x, fmaf(wB, B1v.x, fmaf(wC, C1.x, wD * D1v.x)));
                float g1 = fmaf(wA, A1.y, fmaf(wB, B1v.y, fmaf(wC, C1.y, wD * D1v.y)));
                uint32_t off2 = (uint32_t)pt * (K1P * 2) + (uint32_t)(p * 80 + 64 + 2 * lane) * 2;
                *(uint32_t*)(smb + SM_A1 + off2) = pack_h2(g0, g1);
            }
        }
        __syncthreads();

        // ---- layer 1: [128x240] @ [240x64]; exactly 15 k-tiles ----
        float d[8][4];
#pragma unroll
        for (int nt = 0; nt < 8; nt++)
#pragma unroll
            for (int j = 0; j < 4; j++) d[nt][j] = 0.f;
#pragma unroll 3
        for (int kt = 0; kt < 15; kt++) {
            uint32_t ah[4];
            LDMX4(ah, aOff1 + kt * 32);
#pragma unroll
            for (int nt = 0; nt < 8; nt++) {
                uint32_t bb = bOff1 + nt * (8 * K1P * 2) + kt * 32;
                uint32_t bh0 = ldsb32(bb), bh1 = ldsb32(bb + 16);
                MMA_F16(d[nt], ah, bh0, bh1);
            }
        }
        __syncthreads();   // all warps done reading A1; next gather may overwrite

        // ---- layer 1 -> 2 : bias+relu+pack IN REGISTERS ----
        // acc frag (rows qr/qr+8, cols nt*8+qc*2,+1) == A frag layout for m16n8k16.
        uint32_t af[4][4];
#pragma unroll
        for (int g2 = 0; g2 < 4; g2++) {
            int nA = g2 * 16 + nb, nB = nA + 8;
            af[g2][0] = pack_h2(fmaxf(d[2*g2][0]   + biasf[nA],     0.f),
                                fmaxf(d[2*g2][1]   + biasf[nA + 1], 0.f));
            af[g2][1] = pack_h2(fmaxf(d[2*g2][2]   + biasf[nA],     0.f),
                                fmaxf(d[2*g2][3]   + biasf[nA + 1], 0.f));
            af[g2][2] = pack_h2(fmaxf(d[2*g2+1][0] + biasf[nB],     0.f),
                                fmaxf(d[2*g2+1][1] + biasf[nB + 1], 0.f));
            af[g2][3] = pack_h2(fmaxf(d[2*g2+1][2] + biasf[nB],     0.f),
                                fmaxf(d[2*g2+1][3] + biasf[nB + 1], 0.f));
        }

        // ---- layer 2: A from registers, B2 from smem ----
#pragma unroll
        for (int nt = 0; nt < 8; nt++)
#pragma unroll
            for (int j = 0; j < 4; j++) d[nt][j] = 0.f;
#pragma unroll
        for (int kt = 0; kt < 4; kt++) {
#pragma unroll
            for (int nt = 0; nt < 8; nt++) {
                uint32_t bb = bOff2 + nt * (8 * K2P * 2) + kt * 32;
                uint32_t bh0 = ldsb32(bb), bh1 = ldsb32(bb + 16);
                MMA_F16(d[nt], af[kt], bh0, bh1);
            }
        }

        // ---- layer 2 -> 3 ----
#pragma unroll
        for (int g2 = 0; g2 < 4; g2++) {
            int nA = g2 * 16 + nb, nB = nA + 8;
            af[g2][0] = pack_h2(fmaxf(d[2*g2][0]   + biasf[64 + nA],     0.f),
                                fmaxf(d[2*g2][1]   + biasf[64 + nA + 1], 0.f));
            af[g2][1] = pack_h2(fmaxf(d[2*g2][2]   + biasf[64 + nA],     0.f),
                                fmaxf(d[2*g2][3]   + biasf[64 + nA + 1], 0.f));
            af[g2][2] = pack_h2(fmaxf(d[2*g2+1][0] + biasf[64 + nB],     0.f),
                                fmaxf(d[2*g2+1][1] + biasf[64 + nB + 1], 0.f));
            af[g2][3] = pack_h2(fmaxf(d[2*g2+1][2] + biasf[64 + nB],     0.f),
                                fmaxf(d[2*g2+1][3] + biasf[64 + nB + 1], 0.f));
        }

        // ---- layer 3 ----
#pragma unroll
        for (int nt = 0; nt < 8; nt++)
#pragma unroll
            for (int j = 0; j < 4; j++) d[nt][j] = 0.f;
#pragma unroll
        for (int kt = 0; kt < 4; kt++) {
#pragma unroll
            for (int nt = 0; nt < 8; nt++) {
                uint32_t bb = bOff3 + nt * (8 * K2P * 2) + kt * 32;
                uint32_t bh0 = ldsb32(bb), bh1 = ldsb32(bb + 16);
                MMA_F16(d[nt], af[kt], bh0, bh1);
            }
        }

        // ---- layer 4: relu + dot(W4) + b4 (registers + shuffle) ----
        {
            float accLo = 0.f, accHi = 0.f;
#pragma unroll
            for (int nt = 0; nt < 8; nt++) {
                int n = nt * 8 + nb;
                accLo = fmaf(fmaxf(d[nt][0] + biasf[128 + n], 0.f),     biasf[192 + n],     accLo);
                accLo = fmaf(fmaxf(d[nt][1] + biasf[128 + n + 1], 0.f), biasf[192 + n + 1], accLo);
                accHi = fmaf(fmaxf(d[nt][2] + biasf[128 + n], 0.f),     biasf[192 + n],     accHi);
                accHi = fmaf(fmaxf(d[nt][3] + biasf[128 + n + 1], 0.f), biasf[192 + n + 1], accHi);
            }
            accLo += __shfl_xor_sync(0xFFFFFFFF, accLo, 1);
            accLo += __shfl_xor_sync(0xFFFFFFFF, accLo, 2);
            accHi += __shfl_xor_sync(0xFFFFFFFF, accHi, 1);
            accHi += __shfl_xor_sync(0xFFFFFFFF, accHi, 2);
            if (qc == 0) {
                int base = tile * 128 + m0 + qr;
                out[base] = accLo + biasf[256];
                out[base + 8] = accHi + biasf[256];
            }
        }
    }
}

// ---------------------------------------------------------------------------
extern "C" void kernel_launch(void* const* d_in, const int* in_sizes, int n_in,
                              void* d_out, int out_size) {
    const float* planes = (const float*)d_in[0];
    const float* coords = (const float*)d_in[1];
    const float* W1 = (const float*)d_in[2];
    const float* b1 = (const float*)d_in[3];
    const float* W2 = (const float*)d_in[4];
    const float* b2 = (const float*)d_in[5];
    const float* W3 = (const float*)d_in[6];
    const float* b3 = (const float*)d_in[7];
    const float* W4 = (const float*)d_in[8];
    const float* b4 = (const float*)d_in[9];
    float* out = (float*)d_out;

    dim3 tg(T_NH * T_NW / 32, (T_NC + 31) / 32, T_NB * T_NP);
    transpose_planes_kernel<<<tg, dim3(32, 8)>>>(planes);

    cudaFuncSetAttribute(triplane_mma_kernel,
                         cudaFuncAttributeMaxDynamicSharedMemorySize, SM_TOTAL);
    triplane_mma_kernel<<<296, 256, SM_TOTAL>>>(coords, W1, b1, W2, b2, W3, b3,
                                                W4, b4, out);
}